// round 10
// baseline (speedup 1.0000x reference)
#include <cuda_runtime.h>
#include <cuda_bf16.h>
#include <cfloat>
#include <math.h>
#include <stdint.h>

#define HID    1024
#define HEADC  16002
#define C0LO   16000
#define C0HI   28000
#define P0     256
#define P1     64
#define T0C    12000
#define T1C    8000
#define MAXTOK 4096
#define NCTA   152

#define NTILE   128
#define HTILES  126
#define T0TILES 94
#define T1TILES 63
#define HKC     16
#define T0KC    4
#define T1KC    1

#define A_CHUNK 16384
#define B_CHUNK 16384
#define STAGE   32768
#define NSTAGE  4
#define CS_OFF    131072
#define CL_OFF    139264
#define RLAB_OFF  147456
#define RORIG_OFF 147968
#define MB_OFF    148480
#define GEMM_SMEM 148544

#define SW128(x) ((x) ^ ((((uint32_t)(x)) >> 3) & 0x70u))

// prep dispatch ranges
#define PREP_ZERO    456                       // zero g_S: 456*4096 floats
#define PREP_CONVA   (PREP_ZERO + 2048)        // 2504
#define PREP_W0      (PREP_CONVA + 252 * HKC)  // 6536
#define PREP_W1      (PREP_W0 + 188 * T0KC)    // 7288
#define PREP_TOTAL   (PREP_W1 + 126 * T1KC)    // 7414

// ---------------- scratch ----------------
__device__ __align__(1024) unsigned char g_Wh[(size_t)HTILES * HKC * B_CHUNK];
__device__ __align__(1024) unsigned char g_W0[(size_t)T0TILES * T0KC * B_CHUNK];
__device__ __align__(1024) unsigned char g_W1[(size_t)T1TILES * T1KC * B_CHUNK];
__device__ __align__(1024) unsigned char g_Ah[(size_t)32 * HKC * A_CHUNK];
__device__ __align__(1024) unsigned char g_A0[(size_t)32 * T0KC * A_CHUNK];
__device__ __align__(1024) unsigned char g_A1[(size_t)32 * T1KC * A_CHUNK];
__device__ int   g_idx0[MAXTOK];
__device__ int   g_idx1[MAXTOK];
__device__ int   g_cnt[2];
__device__ __align__(16) float g_S[(size_t)NCTA * 3 * MAXTOK];  // per-CTA sum-exp slots
__device__ float g_lab[3 * MAXTOK];
__device__ float g_loss[MAXTOK];

// ---------------- PTX helpers ----------------
__device__ __forceinline__ uint32_t smem_u32(const void* p) {
    uint32_t a;
    asm("{ .reg .u64 t; cvta.to.shared.u64 t, %1; cvt.u32.u64 %0, t; }" : "=r"(a) : "l"(p));
    return a;
}
#define MBARRIER_INIT(addr, cnt) \
    asm volatile("mbarrier.init.shared.b64 [%0], %1;" :: "r"((uint32_t)(addr)), "r"((uint32_t)(cnt)) : "memory")
#define MBARRIER_EXPECT_TX(addr, tx) \
    asm volatile("mbarrier.arrive.expect_tx.shared.b64 _, [%0], %1;" :: "r"((uint32_t)(addr)), "r"((uint32_t)(tx)) : "memory")
#define MBARRIER_ARRIVE(addr) \
    asm volatile("mbarrier.arrive.shared.b64 _, [%0];" :: "r"((uint32_t)(addr)) : "memory")
#define MBARRIER_WAIT(addr, par) do { \
    uint32_t _m = (uint32_t)(addr); uint32_t _p = (uint32_t)(par); uint32_t _d; \
    asm volatile("{\n\t.reg .pred p;\n\t" \
        "mbarrier.try_wait.parity.acquire.cta.shared::cta.b64 p, [%1], %2;\n\t" \
        "selp.b32 %0, 1, 0, p;\n\t}" : "=r"(_d) : "r"(_m), "r"(_p) : "memory"); \
    if (!_d) { \
        asm volatile("{\n\t.reg .pred P1;\n\t" \
            "WL_%=:\n\t" \
            "mbarrier.try_wait.parity.acquire.cta.shared::cta.b64 P1, [%0], %1, 0x989680;\n\t" \
            "@P1 bra.uni WD_%=;\n\t" \
            "bra.uni WL_%=;\n\t" \
            "WD_%=:\n\t}" :: "r"(_m), "r"(_p) : "memory"); \
    } } while (0)
#define BAR256() asm volatile("bar.sync 1, 256;" ::: "memory")

__device__ __forceinline__ void bulk_g2s(uint32_t dst, const void* src, uint32_t bytes, uint32_t mbar) {
    asm volatile("cp.async.bulk.shared::cluster.global.mbarrier::complete_tx::bytes [%0], [%1], %2, [%3];"
        :: "r"(dst), "l"(src), "r"(bytes), "r"(mbar) : "memory");
}
__device__ __forceinline__ void ldsm4(uint32_t* r, uint32_t addr) {
    asm volatile("ldmatrix.sync.aligned.m8n8.x4.shared.b16 {%0,%1,%2,%3}, [%4];"
        : "=r"(r[0]), "=r"(r[1]), "=r"(r[2]), "=r"(r[3]) : "r"(addr));
}
__device__ __forceinline__ void mma16816(float* d, const uint32_t* a, const uint32_t* b) {
    asm volatile("mma.sync.aligned.m16n8k16.row.col.f32.bf16.bf16.f32 "
        "{%0,%1,%2,%3}, {%4,%5,%6,%7}, {%8,%9}, {%0,%1,%2,%3};"
        : "+f"(d[0]), "+f"(d[1]), "+f"(d[2]), "+f"(d[3])
        : "r"(a[0]), "r"(a[1]), "r"(a[2]), "r"(a[3]), "r"(b[0]), "r"(b[1]));
}
__device__ __forceinline__ uint32_t pack_bf2(float a, float b) {
    __nv_bfloat162 h = __floats2bfloat162_rn(a, b);
    return *reinterpret_cast<uint32_t*>(&h);
}
__device__ __forceinline__ int imin(int a, int b) { return a < b ? a : b; }
__device__ __forceinline__ int imax(int a, int b) { return a > b ? a : b; }

// ---------------- gather ----------------
__global__ void gather_kernel(const int* __restrict__ labels, int ntok)
{
    __shared__ int c0, c1;
    if (threadIdx.x == 0) { c0 = 0; c1 = 0; }
    __syncthreads();
    for (int i = threadIdx.x; i < ntok; i += blockDim.x) {
        int l = labels[i];
        if (l >= C0LO) {
            if (l < C0HI) g_idx0[atomicAdd(&c0, 1)] = i;
            else          g_idx1[atomicAdd(&c1, 1)] = i;
        }
    }
    __syncthreads();
    if (threadIdx.x == 0) { g_cnt[0] = c0; g_cnt[1] = c1; }
}

// ---------------- merged prep: zero g_S + conv_a + conv_w ----------------
__global__ void prep_kernel(const float* __restrict__ inp,
                            const float* __restrict__ head_W,
                            const float* __restrict__ t0_W,
                            const float* __restrict__ t1_W)
{
    __shared__ float ws[64][66];
    const int b = blockIdx.x, tid = threadIdx.x;

    if (b < PREP_ZERO) {
        float4* dst = reinterpret_cast<float4*>(g_S) + (size_t)b * 1024;
        #pragma unroll
        for (int i = 0; i < 4; i++)
            dst[tid + i * 256] = make_float4(0.f, 0.f, 0.f, 0.f);
        return;
    }
    if (b < PREP_CONVA) {
        int idx = (b - PREP_ZERO) * 256 + tid;
        int token = idx >> 7;
        int unit  = idx & 127;
        int kc = unit >> 3, u = unit & 7;
        const float4* src = reinterpret_cast<const float4*>(inp + (size_t)token * HID + kc * 64 + u * 8);
        float4 v0 = src[0], v1 = src[1];
        uint4 o;
        o.x = pack_bf2(v0.x, v0.y); o.y = pack_bf2(v0.z, v0.w);
        o.z = pack_bf2(v1.x, v1.y); o.w = pack_bf2(v1.z, v1.w);
        int r = token & 127;
        size_t off = ((size_t)(token >> 7) * HKC + kc) * A_CHUNK
                   + (r >> 3) * 1024 + SW128((r & 7) * 128 + u * 16);
        *reinterpret_cast<uint4*>(g_Ah + off) = o;
        return;
    }

    const float* W; unsigned char* out; int C, kchunks, nct, r;
    if (b < PREP_W0)      { W = head_W; out = g_Wh; C = HEADC; kchunks = HKC;  nct = 252; r = b - PREP_CONVA; }
    else if (b < PREP_W1) { W = t0_W;   out = g_W0; C = T0C;   kchunks = T0KC; nct = 188; r = b - PREP_W0; }
    else                  { W = t1_W;   out = g_W1; C = T1C;   kchunks = T1KC; nct = 126; r = b - PREP_W1; }
    const int ct = r % nct;
    const int kt = r / nct;

    #pragma unroll
    for (int i = 0; i < 8; i++) {
        int e2 = tid + i * 256;
        int kr = e2 >> 5, c2 = e2 & 31;
        int c = ct * 64 + c2 * 2;
        float2 v;
        if (c + 1 < C) {
            v = *reinterpret_cast<const float2*>(W + (size_t)(kt * 64 + kr) * C + c);
        } else {
            v.x = (c < C) ? W[(size_t)(kt * 64 + kr) * C + c] : 0.f;
            v.y = 0.f;
        }
        *reinterpret_cast<float2*>(&ws[kr][c2 * 2]) = v;
    }
    __syncthreads();
    for (int e = tid; e < 512; e += 256) {
        int n64 = e >> 3, u = e & 7;
        int ng = ct * 64 + n64;
        int tile = ng >> 7, nt = ng & 127;
        uint4 o;
        o.x = pack_bf2(ws[u * 8 + 0][n64], ws[u * 8 + 1][n64]);
        o.y = pack_bf2(ws[u * 8 + 2][n64], ws[u * 8 + 3][n64]);
        o.z = pack_bf2(ws[u * 8 + 4][n64], ws[u * 8 + 5][n64]);
        o.w = pack_bf2(ws[u * 8 + 6][n64], ws[u * 8 + 7][n64]);
        size_t off = ((size_t)(tile * kchunks + kt)) * B_CHUNK
                   + (nt >> 3) * 1024 + SW128((nt & 7) * 128 + u * 16);
        *reinterpret_cast<uint4*>(out + off) = o;
    }
}

// ---------------- merged projections ----------------
__global__ void projs_kernel(const float* __restrict__ inp,
                             const float* __restrict__ t0_pW, const float* __restrict__ t0_pb,
                             const float* __restrict__ t1_pW, const float* __restrict__ t1_pb)
{
    __shared__ float As[8][HID];
    const int tid = threadIdx.x;

    if (blockIdx.x < 512) {
        int n = g_cnt[0];
        int g0 = blockIdx.x * 8;
        if (g0 >= n) return;
        for (int e = tid; e < 8 * HID; e += 256) {
            int r = e >> 10, k = e & 1023;
            int g = g0 + r;
            As[r][k] = (g < n) ? inp[(size_t)g_idx0[g] * HID + k] : 0.f;
        }
        __syncthreads();
        float acc[8];
        #pragma unroll
        for (int t = 0; t < 8; t++) acc[t] = 0.f;
        float bj = t0_pb[tid];
        #pragma unroll 4
        for (int k = 0; k < HID; k++) {
            float w = t0_pW[k * P0 + tid];
            #pragma unroll
            for (int t = 0; t < 8; t++) acc[t] = fmaf(As[t][k], w, acc[t]);
        }
        int kc = tid >> 6, kk = tid & 63;
        #pragma unroll
        for (int t = 0; t < 8; t++) {
            int g = g0 + t;
            if (g < n) {
                int r = g & 127;
                size_t off = ((size_t)(g >> 7) * T0KC + kc) * A_CHUNK
                           + (r >> 3) * 1024 + SW128((r & 7) * 128 + kk * 2);
                *reinterpret_cast<__nv_bfloat16*>(g_A0 + off) = __float2bfloat16(acc[t] + bj);
            }
        }
    } else {
        int n = g_cnt[1];
        int g0 = (blockIdx.x - 512) * 8;
        if (g0 >= n) return;
        for (int e = tid; e < 8 * HID; e += 256) {
            int r = e >> 10, k = e & 1023;
            int g = g0 + r;
            As[r][k] = (g < n) ? inp[(size_t)g_idx1[g] * HID + k] : 0.f;
        }
        __syncthreads();
        int j  = tid & 63;
        int tg = tid >> 6;
        float acc0 = 0.f, acc1 = 0.f;
        float bj = t1_pb[j];
        #pragma unroll 4
        for (int k = 0; k < HID; k++) {
            float w = t1_pW[k * P1 + j];
            acc0 = fmaf(As[tg * 2 + 0][k], w, acc0);
            acc1 = fmaf(As[tg * 2 + 1][k], w, acc1);
        }
        #pragma unroll
        for (int t = 0; t < 2; t++) {
            int g = g0 + tg * 2 + t;
            if (g < n) {
                int r = g & 127;
                float v = (t == 0) ? acc0 : acc1;
                size_t off = ((size_t)(g >> 7)) * A_CHUNK
                           + (r >> 3) * 1024 + SW128((r & 7) * 128 + j * 2);
                *reinterpret_cast<__nv_bfloat16*>(g_A1 + off) = __float2bfloat16(v + bj);
            }
        }
    }
}

// ---------------- persistent balanced GEMM + sum-exp CE ----------------
__global__ void __launch_bounds__(288, 1)
gemm_ce_all(const float* __restrict__ head_b, const float* __restrict__ t0_b,
            const float* __restrict__ t1_b, const int* __restrict__ labels, int ntok)
{
    extern __shared__ unsigned char sm[];
    uint32_t sb = smem_u32(sm);
    const int tid = threadIdx.x, wid = tid >> 5, lane = tid & 31;

    float* cs = reinterpret_cast<float*>(sm + CS_OFF);
    float* cl = reinterpret_cast<float*>(sm + CL_OFF);
    int* rlabs = reinterpret_cast<int*>(sm + RLAB_OFF);
    int* rorig = reinterpret_cast<int*>(sm + RORIG_OFF);

    const int nmh = ntok >> 7;
    const int nm0 = (g_cnt[0] + 127) >> 7;
    const int nm1 = (g_cnt[1] + 127) >> 7;
    const int Ja[3]  = { nmh * HTILES, nm0 * T0TILES, nm1 * T1TILES };
    const int WKa[3] = { 16, 4, 1 };
    const int BAS0 = 0, BAS1 = Ja[0] * 16, BAS2 = BAS1 + Ja[1] * 4;
    const int BASa[3] = { BAS0, BAS1, BAS2 };
    const int Wtot = BAS2 + Ja[2];
    const int s = (int)(((long long)blockIdx.x * Wtot) / NCTA);
    const int e = (int)(((long long)(blockIdx.x + 1) * Wtot) / NCTA);

    const unsigned char* Aptr[3] = { g_Ah, g_A0, g_A1 };
    const unsigned char* Bptr[3] = { g_Wh, g_W0, g_W1 };
    const float* bptr[3] = { head_b, t0_b, t1_b };
    const int TILa[3] = { HTILES, T0TILES, T1TILES };
    const int KCa[3]  = { HKC, T0KC, T1KC };
    const int Ca[3]   = { HEADC, T0C, T1C };

    if (tid == 0) {
        #pragma unroll
        for (int st = 0; st < NSTAGE; st++) {
            MBARRIER_INIT(sb + MB_OFF + st * 8, 1);
            MBARRIER_INIT(sb + MB_OFF + 32 + st * 8, 256);
        }
    }
    __syncthreads();

    if (wid == 8) {
        if (lane == 0) {
            int cc = 0;
            #pragma unroll
            for (int k = 0; k < 3; k++) {
                const int wk = WKa[k], lim = Ja[k] * wk;
                const int lo = imin(imax(s - BASa[k], 0), lim);
                const int hi = imin(imax(e - BASa[k], 0), lim);
                const int jb = (lo + wk - 1) / wk, je = (hi + wk - 1) / wk;
                #pragma unroll 1
                for (int j = jb; j < je; j++) {
                    const int mb = j / TILa[k], tl = j - mb * TILa[k];
                    #pragma unroll 1
                    for (int kc = 0; kc < KCa[k]; kc++, cc++) {
                        const int st = cc & 3, wr = cc >> 2;
                        const uint32_t fb = sb + MB_OFF + st * 8;
                        const uint32_t eb = sb + MB_OFF + 32 + st * 8;
                        if (cc >= NSTAGE) MBARRIER_WAIT(eb, (wr - 1) & 1);
                        MBARRIER_EXPECT_TX(fb, A_CHUNK + B_CHUNK);
                        bulk_g2s(sb + st * STAGE, Aptr[k] + ((size_t)mb * KCa[k] + kc) * A_CHUNK, A_CHUNK, fb);
                        bulk_g2s(sb + st * STAGE + A_CHUNK, Bptr[k] + ((size_t)tl * KCa[k] + kc) * B_CHUNK, B_CHUNK, fb);
                    }
                }
            }
        }
        return;
    }

    const int wm = wid >> 2, wn = wid & 3;
    const int tq = lane >> 2, tc = lane & 3;
    const int sub = lane >> 3, li = lane & 7;
    const uint32_t vx = (uint32_t)li << 4;
    uint32_t aoff[4], boff[2];
    {
        int arowadd = (sub & 1) * 8;
        #pragma unroll
        for (int mt = 0; mt < 4; mt++) {
            int row = wm * 64 + mt * 16 + arowadd + li;
            aoff[mt] = ((uint32_t)(row >> 3) << 10) + ((uint32_t)li << 7);
        }
        int browadd = (sub >> 1) * 8;
        #pragma unroll
        for (int nb = 0; nb < 2; nb++) {
            int row = wn * 32 + nb * 16 + browadd + li;
            boff[nb] = ((uint32_t)(row >> 3) << 10) + ((uint32_t)li << 7);
        }
    }
    const uint32_t auo = (uint32_t)(sub >> 1) << 4;
    const uint32_t buo = (uint32_t)(sub & 1) << 4;

    float rs[4][2], rl[4][2];
    int rlb[4][2];
    int cur_kid = -1, cur_mb = -1;
    int cc = 0;

    auto flushseg = [&]() {
        if (cur_kid >= 0) {
            #pragma unroll
            for (int mt = 0; mt < 4; mt++)
                #pragma unroll
                for (int h = 0; h < 2; h++) {
                    int r = wm * 64 + mt * 16 + tq + h * 8;
                    int p = wn * 4 + tc;
                    cs[r * 16 + p] = rs[mt][h];
                    cl[r * 16 + p] = rl[mt][h];
                }
            BAR256();
            if (tid < 128) {
                float S = 0.f, L = -FLT_MAX;
                #pragma unroll 4
                for (int p = 0; p < 16; p++) {
                    S += cs[tid * 16 + p];
                    L = fmaxf(L, cl[tid * 16 + p]);
                }
                int orig = rorig[tid];
                if (orig >= 0) {
                    g_S[((size_t)blockIdx.x * 3 + cur_kid) * MAXTOK + orig] = S;
                    if (L > -1e37f) g_lab[cur_kid * MAXTOK + orig] = L;
                }
            }
            BAR256();
        }
    };
    auto loadseg = [&](int k, int mb) {
        if (tid < 128) {
            if (k == 0) {
                int orig = mb * 128 + tid;
                int l = labels[orig];
                rlabs[tid] = (l < C0LO) ? l : ((l < C0HI) ? C0LO : C0LO + 1);
                rorig[tid] = orig;
            } else {
                int n = g_cnt[k - 1];
                int g = mb * 128 + tid;
                if (g < n) {
                    int o = ((k == 1) ? g_idx0 : g_idx1)[g];
                    rorig[tid] = o;
                    rlabs[tid] = labels[o] - ((k == 1) ? C0LO : C0HI);
                } else { rorig[tid] = -1; rlabs[tid] = -2; }
            }
        }
        BAR256();
        #pragma unroll
        for (int mt = 0; mt < 4; mt++)
            #pragma unroll
            for (int h = 0; h < 2; h++) {
                rs[mt][h] = 0.f; rl[mt][h] = -FLT_MAX;
                rlb[mt][h] = rlabs[wm * 64 + mt * 16 + tq + h * 8];
            }
    };

    #pragma unroll
    for (int k = 0; k < 3; k++) {
        const int wk = WKa[k], lim = Ja[k] * wk;
        const int lo = imin(imax(s - BASa[k], 0), lim);
        const int hi = imin(imax(e - BASa[k], 0), lim);
        const int jb = (lo + wk - 1) / wk, je = (hi + wk - 1) / wk;
        const int TIL = TILa[k], KC = KCa[k], C = Ca[k];
        const float* bias = bptr[k];
        #pragma unroll 1
        for (int j = jb; j < je; j++) {
            const int mb = j / TIL, tl = j - mb * TIL;
            if (k != cur_kid || mb != cur_mb) {
                flushseg();
                loadseg(k, mb);
                cur_kid = k; cur_mb = mb;
            }
            float acc[4][4][4];
            #pragma unroll
            for (int mt = 0; mt < 4; mt++)
                #pragma unroll
                for (int nt = 0; nt < 4; nt++)
                    #pragma unroll
                    for (int q = 0; q < 4; q++) acc[mt][nt][q] = 0.f;

            #pragma unroll 1
            for (int kc = 0; kc < KC; kc++, cc++) {
                const int st = cc & 3, wr = cc >> 2;
                const uint32_t fb = sb + MB_OFF + st * 8;
                const uint32_t eb = sb + MB_OFF + 32 + st * 8;
                MBARRIER_WAIT(fb, wr & 1);
                const uint32_t Ab = sb + st * STAGE;
                const uint32_t Bb = Ab + A_CHUNK;
                #pragma unroll
                for (int ks = 0; ks < 4; ks++) {
                    const uint32_t kx = (uint32_t)ks << 5;
                    uint32_t a[4][4], bfr[4][2];
                    #pragma unroll
                    for (int mt = 0; mt < 4; mt++)
                        ldsm4(a[mt], Ab + aoff[mt] + ((kx + auo) ^ vx));
                    #pragma unroll
                    for (int nb = 0; nb < 2; nb++) {
                        uint32_t t4[4];
                        ldsm4(t4, Bb + boff[nb] + ((kx + buo) ^ vx));
                        bfr[nb * 2 + 0][0] = t4[0]; bfr[nb * 2 + 0][1] = t4[1];
                        bfr[nb * 2 + 1][0] = t4[2]; bfr[nb * 2 + 1][1] = t4[3];
                    }
                    #pragma unroll
                    for (int mt = 0; mt < 4; mt++)
                        #pragma unroll
                        for (int nt = 0; nt < 4; nt++)
                            mma16816(acc[mt][nt], a[mt], bfr[nt]);
                }
                MBARRIER_ARRIVE(eb);
            }
            const int cb0 = tl * NTILE + wn * 32 + tc * 2;
            #pragma unroll
            for (int mt = 0; mt < 4; mt++)
                #pragma unroll
                for (int h = 0; h < 2; h++) {
                    #pragma unroll
                    for (int nt = 0; nt < 4; nt++)
                        #pragma unroll
                        for (int q = 0; q < 2; q++) {
                            int c = cb0 + nt * 8 + q;
                            if (c < C) {
                                float x = acc[mt][nt][h * 2 + q] + __ldg(bias + c);
                                rs[mt][h] += __expf(x);
                                if (c == rlb[mt][h]) rl[mt][h] = x;
                            }
                        }
                }
        }
    }
    flushseg();
}

// ---------------- finalize ----------------
__global__ void finalize1_kernel(const int* __restrict__ labels, int ntok)
{
    int t = blockIdx.x * 256 + threadIdx.x;
    if (t >= ntok) return;
    int l = labels[t];
    float SH = 0.f;
    for (int i = 0; i < NCTA; i++)
        SH += g_S[((size_t)i * 3 + 0) * MAXTOK + t];
    float loss = logf(SH) - g_lab[0 * MAXTOK + t];
    if (l >= C0LO) {
        int kid = (l < C0HI) ? 1 : 2;
        float ST = 0.f;
        for (int i = 0; i < NCTA; i++)
            ST += g_S[((size_t)i * 3 + kid) * MAXTOK + t];
        loss += logf(ST) - g_lab[kid * MAXTOK + t];
    }
    if (l == 0) loss = 0.f;
    g_loss[t] = loss;
}

__global__ void finalize2_kernel(float* __restrict__ out, int ntok)
{
    __shared__ float red[32];
    int tid = threadIdx.x;
    float local = 0.f;
    for (int t = tid; t < ntok; t += blockDim.x) local += g_loss[t];
    #pragma unroll
    for (int o = 16; o > 0; o >>= 1) local += __shfl_xor_sync(0xffffffffu, local, o);
    if ((tid & 31) == 0) red[tid >> 5] = local;
    __syncthreads();
    if (tid < 32) {
        float v = red[tid];
        #pragma unroll
        for (int o = 16; o > 0; o >>= 1) v += __shfl_xor_sync(0xffffffffu, v, o);
        if (tid == 0) out[0] = v / (float)ntok;
    }
}

// ---------------- host launch ----------------
extern "C" void kernel_launch(void* const* d_in, const int* in_sizes, int n_in,
                              void* d_out, int out_size)
{
    const float* inp    = (const float*)d_in[0];
    const int*   labels = (const int*)  d_in[1];
    const float* head_W = (const float*)d_in[2];
    const float* head_b = (const float*)d_in[3];
    const float* t0_pW  = (const float*)d_in[4];
    const float* t0_pb  = (const float*)d_in[5];
    const float* t0_W   = (const float*)d_in[6];
    const float* t0_b   = (const float*)d_in[7];
    const float* t1_pW  = (const float*)d_in[8];
    const float* t1_pb  = (const float*)d_in[9];
    const float* t1_W   = (const float*)d_in[10];
    const float* t1_b   = (const float*)d_in[11];
    const int ntok = in_sizes[1];   // 4096

    cudaFuncSetAttribute(gemm_ce_all, cudaFuncAttributeMaxDynamicSharedMemorySize, GEMM_SMEM);

    prep_kernel<<<PREP_TOTAL, 256>>>(inp, head_W, t0_W, t1_W);
    gather_kernel<<<1, 256>>>(labels, ntok);
    projs_kernel<<<1024, 256>>>(inp, t0_pW, t0_pb, t1_pW, t1_pb);
    gemm_ce_all<<<NCTA, 288, GEMM_SMEM>>>(head_b, t0_b, t1_b, labels, ntok);
    finalize1_kernel<<<(MAXTOK + 255) / 256, 256>>>(labels, ntok);
    finalize2_kernel<<<1, 1024>>>((float*)d_out, ntok);
}

// round 11
// speedup vs baseline: 2.3347x; 2.3347x over previous
#include <cuda_runtime.h>
#include <cuda_bf16.h>
#include <cfloat>
#include <math.h>
#include <stdint.h>

#define HID    1024
#define HEADC  16002
#define C0LO   16000
#define C0HI   28000
#define P0     256
#define P1     64
#define T0C    12000
#define T1C    8000
#define MAXTOK 4096

#define NTILE   128
#define HTILES  126
#define T0TILES 94
#define T1TILES 63
#define HKC     16
#define T0KC    4
#define T1KC    1

#define A_CHUNK 16384
#define B_CHUNK 16384
#define STAGE   32768
#define NSTAGE  4
#define CS_OFF    131072
#define CL_OFF    139264
#define RLAB_OFF  147456
#define RORIG_OFF 147968
#define MB_OFF    148480
#define GEMM_SMEM 148544

#define SW128(x) ((x) ^ ((((uint32_t)(x)) >> 3) & 0x70u))

// prep dispatch ranges
#define PREP_CONVA   2048
#define PREP_W0      (PREP_CONVA + 252 * HKC)    // 6080
#define PREP_W1      (PREP_W0 + 188 * T0KC)      // 6832
#define PREP_TOTAL   (PREP_W1 + 126 * T1KC)      // 6958

// ---------------- scratch ----------------
__device__ __align__(1024) unsigned char g_Wh[(size_t)HTILES * HKC * B_CHUNK];
__device__ __align__(1024) unsigned char g_W0[(size_t)T0TILES * T0KC * B_CHUNK];
__device__ __align__(1024) unsigned char g_W1[(size_t)T1TILES * T1KC * B_CHUNK];
__device__ __align__(1024) unsigned char g_Ah[(size_t)32 * HKC * A_CHUNK];
__device__ __align__(1024) unsigned char g_A0[(size_t)32 * T0KC * A_CHUNK];
__device__ __align__(1024) unsigned char g_A1[(size_t)32 * T1KC * A_CHUNK];
__device__ int   g_idx0[MAXTOK];
__device__ int   g_idx1[MAXTOK];
__device__ int   g_cnt[2];
__device__ float g_pt[3][2][4][MAXTOK];  // [kind][S/lab][split][token]

// ---------------- PTX helpers ----------------
__device__ __forceinline__ uint32_t smem_u32(const void* p) {
    uint32_t a;
    asm("{ .reg .u64 t; cvta.to.shared.u64 t, %1; cvt.u32.u64 %0, t; }" : "=r"(a) : "l"(p));
    return a;
}
#define MBARRIER_INIT(addr, cnt) \
    asm volatile("mbarrier.init.shared.b64 [%0], %1;" :: "r"((uint32_t)(addr)), "r"((uint32_t)(cnt)) : "memory")
#define MBARRIER_EXPECT_TX(addr, tx) \
    asm volatile("mbarrier.arrive.expect_tx.shared.b64 _, [%0], %1;" :: "r"((uint32_t)(addr)), "r"((uint32_t)(tx)) : "memory")
#define MBARRIER_ARRIVE(addr) \
    asm volatile("mbarrier.arrive.shared.b64 _, [%0];" :: "r"((uint32_t)(addr)) : "memory")
#define MBARRIER_WAIT(addr, par) do { \
    uint32_t _m = (uint32_t)(addr); uint32_t _p = (uint32_t)(par); uint32_t _d; \
    asm volatile("{\n\t.reg .pred p;\n\t" \
        "mbarrier.try_wait.parity.acquire.cta.shared::cta.b64 p, [%1], %2;\n\t" \
        "selp.b32 %0, 1, 0, p;\n\t}" : "=r"(_d) : "r"(_m), "r"(_p) : "memory"); \
    if (!_d) { \
        asm volatile("{\n\t.reg .pred P1;\n\t" \
            "WL_%=:\n\t" \
            "mbarrier.try_wait.parity.acquire.cta.shared::cta.b64 P1, [%0], %1, 0x989680;\n\t" \
            "@P1 bra.uni WD_%=;\n\t" \
            "bra.uni WL_%=;\n\t" \
            "WD_%=:\n\t}" :: "r"(_m), "r"(_p) : "memory"); \
    } } while (0)
#define BAR256() asm volatile("bar.sync 1, 256;" ::: "memory")

__device__ __forceinline__ void bulk_g2s(uint32_t dst, const void* src, uint32_t bytes, uint32_t mbar) {
    asm volatile("cp.async.bulk.shared::cluster.global.mbarrier::complete_tx::bytes [%0], [%1], %2, [%3];"
        :: "r"(dst), "l"(src), "r"(bytes), "r"(mbar) : "memory");
}
__device__ __forceinline__ void ldsm4(uint32_t* r, uint32_t addr) {
    asm volatile("ldmatrix.sync.aligned.m8n8.x4.shared.b16 {%0,%1,%2,%3}, [%4];"
        : "=r"(r[0]), "=r"(r[1]), "=r"(r[2]), "=r"(r[3]) : "r"(addr));
}
__device__ __forceinline__ void mma16816(float* d, const uint32_t* a, const uint32_t* b) {
    asm volatile("mma.sync.aligned.m16n8k16.row.col.f32.bf16.bf16.f32 "
        "{%0,%1,%2,%3}, {%4,%5,%6,%7}, {%8,%9}, {%0,%1,%2,%3};"
        : "+f"(d[0]), "+f"(d[1]), "+f"(d[2]), "+f"(d[3])
        : "r"(a[0]), "r"(a[1]), "r"(a[2]), "r"(a[3]), "r"(b[0]), "r"(b[1]));
}
__device__ __forceinline__ uint32_t pack_bf2(float a, float b) {
    __nv_bfloat162 h = __floats2bfloat162_rn(a, b);
    return *reinterpret_cast<uint32_t*>(&h);
}

// ---------------- gather ----------------
__global__ void gather_kernel(const int* __restrict__ labels, int ntok)
{
    __shared__ int c0, c1;
    if (threadIdx.x == 0) { c0 = 0; c1 = 0; }
    __syncthreads();
    for (int i = threadIdx.x; i < ntok; i += blockDim.x) {
        int l = labels[i];
        if (l >= C0LO) {
            if (l < C0HI) g_idx0[atomicAdd(&c0, 1)] = i;
            else          g_idx1[atomicAdd(&c1, 1)] = i;
        }
    }
    __syncthreads();
    if (threadIdx.x == 0) { g_cnt[0] = c0; g_cnt[1] = c1; }
}

// ---------------- merged prep: conv_a + conv_w ----------------
__global__ void prep_kernel(const float* __restrict__ inp,
                            const float* __restrict__ head_W,
                            const float* __restrict__ t0_W,
                            const float* __restrict__ t1_W)
{
    __shared__ float ws[64][66];
    const int b = blockIdx.x, tid = threadIdx.x;

    if (b < PREP_CONVA) {
        int idx = b * 256 + tid;
        int token = idx >> 7;
        int unit  = idx & 127;
        int kc = unit >> 3, u = unit & 7;
        const float4* src = reinterpret_cast<const float4*>(inp + (size_t)token * HID + kc * 64 + u * 8);
        float4 v0 = src[0], v1 = src[1];
        uint4 o;
        o.x = pack_bf2(v0.x, v0.y); o.y = pack_bf2(v0.z, v0.w);
        o.z = pack_bf2(v1.x, v1.y); o.w = pack_bf2(v1.z, v1.w);
        int r = token & 127;
        size_t off = ((size_t)(token >> 7) * HKC + kc) * A_CHUNK
                   + (r >> 3) * 1024 + SW128((r & 7) * 128 + u * 16);
        *reinterpret_cast<uint4*>(g_Ah + off) = o;
        return;
    }

    const float* W; unsigned char* out; int C, kchunks, nct, r;
    if (b < PREP_W0)      { W = head_W; out = g_Wh; C = HEADC; kchunks = HKC;  nct = 252; r = b - PREP_CONVA; }
    else if (b < PREP_W1) { W = t0_W;   out = g_W0; C = T0C;   kchunks = T0KC; nct = 188; r = b - PREP_W0; }
    else                  { W = t1_W;   out = g_W1; C = T1C;   kchunks = T1KC; nct = 126; r = b - PREP_W1; }
    const int ct = r % nct;
    const int kt = r / nct;

    #pragma unroll
    for (int i = 0; i < 8; i++) {
        int e2 = tid + i * 256;
        int kr = e2 >> 5, c2 = e2 & 31;
        int c = ct * 64 + c2 * 2;
        float2 v;
        if (c + 1 < C) {
            v = *reinterpret_cast<const float2*>(W + (size_t)(kt * 64 + kr) * C + c);
        } else {
            v.x = (c < C) ? W[(size_t)(kt * 64 + kr) * C + c] : 0.f;
            v.y = 0.f;
        }
        *reinterpret_cast<float2*>(&ws[kr][c2 * 2]) = v;
    }
    __syncthreads();
    for (int e = tid; e < 512; e += 256) {
        int n64 = e >> 3, u = e & 7;
        int ng = ct * 64 + n64;
        int tile = ng >> 7, nt = ng & 127;
        uint4 o;
        o.x = pack_bf2(ws[u * 8 + 0][n64], ws[u * 8 + 1][n64]);
        o.y = pack_bf2(ws[u * 8 + 2][n64], ws[u * 8 + 3][n64]);
        o.z = pack_bf2(ws[u * 8 + 4][n64], ws[u * 8 + 5][n64]);
        o.w = pack_bf2(ws[u * 8 + 6][n64], ws[u * 8 + 7][n64]);
        size_t off = ((size_t)(tile * kchunks + kt)) * B_CHUNK
                   + (nt >> 3) * 1024 + SW128((nt & 7) * 128 + u * 16);
        *reinterpret_cast<uint4*>(out + off) = o;
    }
}

// ---------------- merged projections ----------------
__global__ void projs_kernel(const float* __restrict__ inp,
                             const float* __restrict__ t0_pW, const float* __restrict__ t0_pb,
                             const float* __restrict__ t1_pW, const float* __restrict__ t1_pb)
{
    __shared__ float As[8][HID];
    const int tid = threadIdx.x;

    if (blockIdx.x < 512) {
        int n = g_cnt[0];
        int g0 = blockIdx.x * 8;
        if (g0 >= n) return;
        for (int e = tid; e < 8 * HID; e += 256) {
            int r = e >> 10, k = e & 1023;
            int g = g0 + r;
            As[r][k] = (g < n) ? inp[(size_t)g_idx0[g] * HID + k] : 0.f;
        }
        __syncthreads();
        float acc[8];
        #pragma unroll
        for (int t = 0; t < 8; t++) acc[t] = 0.f;
        float bj = t0_pb[tid];
        #pragma unroll 4
        for (int k = 0; k < HID; k++) {
            float w = t0_pW[k * P0 + tid];
            #pragma unroll
            for (int t = 0; t < 8; t++) acc[t] = fmaf(As[t][k], w, acc[t]);
        }
        int kc = tid >> 6, kk = tid & 63;
        #pragma unroll
        for (int t = 0; t < 8; t++) {
            int g = g0 + t;
            if (g < n) {
                int r = g & 127;
                size_t off = ((size_t)(g >> 7) * T0KC + kc) * A_CHUNK
                           + (r >> 3) * 1024 + SW128((r & 7) * 128 + kk * 2);
                *reinterpret_cast<__nv_bfloat16*>(g_A0 + off) = __float2bfloat16(acc[t] + bj);
            }
        }
    } else {
        int n = g_cnt[1];
        int g0 = (blockIdx.x - 512) * 8;
        if (g0 >= n) return;
        for (int e = tid; e < 8 * HID; e += 256) {
            int r = e >> 10, k = e & 1023;
            int g = g0 + r;
            As[r][k] = (g < n) ? inp[(size_t)g_idx1[g] * HID + k] : 0.f;
        }
        __syncthreads();
        int j  = tid & 63;
        int tg = tid >> 6;
        float acc0 = 0.f, acc1 = 0.f;
        float bj = t1_pb[j];
        #pragma unroll 4
        for (int k = 0; k < HID; k++) {
            float w = t1_pW[k * P1 + j];
            acc0 = fmaf(As[tg * 2 + 0][k], w, acc0);
            acc1 = fmaf(As[tg * 2 + 1][k], w, acc1);
        }
        #pragma unroll
        for (int t = 0; t < 2; t++) {
            int g = g0 + tg * 2 + t;
            if (g < n) {
                int r = g & 127;
                float v = (t == 0) ? acc0 : acc1;
                size_t off = ((size_t)(g >> 7)) * A_CHUNK
                           + (r >> 3) * 1024 + SW128((r & 7) * 128 + j * 2);
                *reinterpret_cast<__nv_bfloat16*>(g_A1 + off) = __float2bfloat16(v + bj);
            }
        }
    }
}

// ---------------- fused mma.sync GEMM + sum-exp CE (R8 topology) ----------------
// grid (4 splits, 96): y<32 head, y<64 tail0, else tail1.
// 8 MMA warps (2m x 4n) + dedicated producer warp (wid 8), 4-stage ring.
__global__ void __launch_bounds__(288, 1)
gemm_ce_all(const float* __restrict__ head_b, const float* __restrict__ t0_b,
            const float* __restrict__ t1_b, const int* __restrict__ labels)
{
    const int split = blockIdx.x, my = blockIdx.y;
    int kid, mblock;
    const float* bias;
    const unsigned char *Asw, *Bsw;
    int C, kchunks, tiles_total, lo;
    if (my < 32)      { kid = 0; mblock = my;      bias = head_b; Asw = g_Ah; Bsw = g_Wh; C = HEADC; kchunks = HKC;  tiles_total = HTILES;  lo = 0; }
    else if (my < 64) { kid = 1; mblock = my - 32; bias = t0_b;   Asw = g_A0; Bsw = g_W0; C = T0C;   kchunks = T0KC; tiles_total = T0TILES; lo = C0LO; }
    else              { kid = 2; mblock = my - 64; bias = t1_b;   Asw = g_A1; Bsw = g_W1; C = T1C;   kchunks = T1KC; tiles_total = T1TILES; lo = C0HI; }
    if (kid != 0 && mblock * 128 >= g_cnt[kid - 1]) return;

    extern __shared__ unsigned char sm[];
    uint32_t sb = smem_u32(sm);
    const int tid = threadIdx.x, wid = tid >> 5, lane = tid & 31;

    const int q4 = tiles_total >> 2, rem = tiles_total & 3;
    const int tbeg = split * q4 + min(split, rem);
    const int tcnt = q4 + (split < rem ? 1 : 0);
    const int total = tcnt * kchunks;

    float* cs = reinterpret_cast<float*>(sm + CS_OFF);
    float* cl = reinterpret_cast<float*>(sm + CL_OFF);
    int* rlabs = reinterpret_cast<int*>(sm + RLAB_OFF);
    int* rorig = reinterpret_cast<int*>(sm + RORIG_OFF);

    if (tid == 0) {
        #pragma unroll
        for (int s = 0; s < NSTAGE; s++) {
            MBARRIER_INIT(sb + MB_OFF + s * 8, 1);         // full[s]
            MBARRIER_INIT(sb + MB_OFF + 32 + s * 8, 256);  // empty[s]
        }
    }
    if (tid < 128) {
        if (kid == 0) {
            int orig = mblock * 128 + tid;
            int l = labels[orig];
            rlabs[tid] = (l < C0LO) ? l : ((l < C0HI) ? C0LO : C0LO + 1);
            rorig[tid] = orig;
        } else {
            int n = g_cnt[kid - 1];
            int g = mblock * 128 + tid;
            if (g < n) {
                int o = ((kid == 1) ? g_idx0 : g_idx1)[g];
                rorig[tid] = o; rlabs[tid] = labels[o] - lo;
            } else { rorig[tid] = -1; rlabs[tid] = -2; }
        }
    }
    __syncthreads();

    if (wid == 8) {
        // ---------------- dedicated producer ----------------
        if (lane == 0) {
            #pragma unroll 1
            for (int cc = 0; cc < total; cc++) {
                int st = cc & (NSTAGE - 1), ph = cc >> 2;
                uint32_t fb = sb + MB_OFF + st * 8;
                uint32_t eb = sb + MB_OFF + 32 + st * 8;
                if (cc >= NSTAGE) MBARRIER_WAIT(eb, (ph - 1) & 1);
                MBARRIER_EXPECT_TX(fb, A_CHUNK + B_CHUNK);
                int tile = tbeg + cc / kchunks, kc = cc % kchunks;
                bulk_g2s(sb + st * STAGE, Asw + ((size_t)mblock * kchunks + kc) * A_CHUNK, A_CHUNK, fb);
                bulk_g2s(sb + st * STAGE + A_CHUNK, Bsw + ((size_t)tile * kchunks + kc) * B_CHUNK, B_CHUNK, fb);
            }
        }
        return;
    }

    // ---------------- MMA consumers ----------------
    const int wm = wid >> 2, wn = wid & 3;
    const int tq = lane >> 2, tc = lane & 3;
    const int sub = lane >> 3, li = lane & 7;
    const uint32_t vx = (uint32_t)li << 4;
    uint32_t aoff[4], boff[2];
    {
        int arowadd = (sub & 1) * 8;
        #pragma unroll
        for (int mt = 0; mt < 4; mt++) {
            int row = wm * 64 + mt * 16 + arowadd + li;
            aoff[mt] = ((uint32_t)(row >> 3) << 10) + ((uint32_t)li << 7);
        }
        int browadd = (sub >> 1) * 8;
        #pragma unroll
        for (int nb = 0; nb < 2; nb++) {
            int row = wn * 32 + nb * 16 + browadd + li;
            boff[nb] = ((uint32_t)(row >> 3) << 10) + ((uint32_t)li << 7);
        }
    }
    const uint32_t auo = (uint32_t)(sub >> 1) << 4;
    const uint32_t buo = (uint32_t)(sub & 1) << 4;

    // running sum-exp + label logit per (mtile, half)
    float rs[4][2], rl[4][2];
    int rlb[4][2];
    #pragma unroll
    for (int mt = 0; mt < 4; mt++)
        #pragma unroll
        for (int h = 0; h < 2; h++) {
            rs[mt][h] = 0.f; rl[mt][h] = -FLT_MAX;
            rlb[mt][h] = rlabs[wm * 64 + mt * 16 + tq + h * 8];
        }

    int cc = 0;
    #pragma unroll 1
    for (int tt = 0; tt < tcnt; tt++) {
        float acc[4][4][4];
        #pragma unroll
        for (int mt = 0; mt < 4; mt++)
            #pragma unroll
            for (int nt = 0; nt < 4; nt++)
                #pragma unroll
                for (int q = 0; q < 4; q++) acc[mt][nt][q] = 0.f;

        #pragma unroll 1
        for (int kc = 0; kc < kchunks; kc++, cc++) {
            const int st = cc & (NSTAGE - 1), ph = cc >> 2;
            const uint32_t fb = sb + MB_OFF + st * 8;
            const uint32_t eb = sb + MB_OFF + 32 + st * 8;
            MBARRIER_WAIT(fb, ph & 1);
            const uint32_t Ab = sb + st * STAGE;
            const uint32_t Bb = Ab + A_CHUNK;
            #pragma unroll
            for (int ks = 0; ks < 4; ks++) {
                const uint32_t kx = (uint32_t)ks << 5;
                uint32_t a[4][4], bfr[4][2];
                #pragma unroll
                for (int mt = 0; mt < 4; mt++)
                    ldsm4(a[mt], Ab + aoff[mt] + ((kx + auo) ^ vx));
                #pragma unroll
                for (int nb = 0; nb < 2; nb++) {
                    uint32_t t4[4];
                    ldsm4(t4, Bb + boff[nb] + ((kx + buo) ^ vx));
                    bfr[nb * 2 + 0][0] = t4[0]; bfr[nb * 2 + 0][1] = t4[1];
                    bfr[nb * 2 + 1][0] = t4[2]; bfr[nb * 2 + 1][1] = t4[3];
                }
                #pragma unroll
                for (int mt = 0; mt < 4; mt++)
                    #pragma unroll
                    for (int nt = 0; nt < 4; nt++)
                        mma16816(acc[mt][nt], a[mt], bfr[nt]);
            }
            MBARRIER_ARRIVE(eb);
        }
        // ---- epilogue: plain sum-exp (logits bounded; validated in R10) ----
        const int cb0 = (tbeg + tt) * NTILE + wn * 32 + tc * 2;
        #pragma unroll
        for (int mt = 0; mt < 4; mt++)
            #pragma unroll
            for (int h = 0; h < 2; h++) {
                #pragma unroll
                for (int nt = 0; nt < 4; nt++)
                    #pragma unroll
                    for (int q = 0; q < 2; q++) {
                        int c = cb0 + nt * 8 + q;
                        if (c < C) {
                            float x = acc[mt][nt][h * 2 + q] + __ldg(bias + c);
                            rs[mt][h] += __expf(x);
                            if (c == rlb[mt][h]) rl[mt][h] = x;
                        }
                    }
            }
    }

    // ---- cross-warp combine (16 partials per row) ----
    #pragma unroll
    for (int mt = 0; mt < 4; mt++)
        #pragma unroll
        for (int h = 0; h < 2; h++) {
            int r = wm * 64 + mt * 16 + tq + h * 8;
            int p = wn * 4 + tc;
            cs[r * 16 + p] = rs[mt][h];
            cl[r * 16 + p] = rl[mt][h];
        }
    BAR256();
    if (tid < 128) {
        float S = 0.f, L = -FLT_MAX;
        #pragma unroll 4
        for (int p = 0; p < 16; p++) {
            S += cs[tid * 16 + p];
            L = fmaxf(L, cl[tid * 16 + p]);
        }
        int orig = rorig[tid];
        if (orig >= 0) {
            g_pt[kid][0][split][orig] = S;
            g_pt[kid][1][split][orig] = L;
        }
    }
}

// ---------------- finalize: combine splits, mask, mean ----------------
__global__ void finalize_kernel(const int* __restrict__ labels, float* __restrict__ out, int ntok)
{
    __shared__ float red[32];
    int tid = threadIdx.x;
    float local = 0.f;
    for (int t = tid; t < ntok; t += blockDim.x) {
        float SH = 0.f, LH = -FLT_MAX;
        #pragma unroll
        for (int s = 0; s < 4; s++) {
            SH += g_pt[0][0][s][t];
            LH = fmaxf(LH, g_pt[0][1][s][t]);
        }
        float loss = logf(SH) - LH;
        int l = labels[t];
        if (l >= C0LO) {
            int kid = (l < C0HI) ? 1 : 2;
            float ST = 0.f, LT = -FLT_MAX;
            #pragma unroll
            for (int s = 0; s < 4; s++) {
                ST += g_pt[kid][0][s][t];
                LT = fmaxf(LT, g_pt[kid][1][s][t]);
            }
            loss += logf(ST) - LT;
        }
        if (l == 0) loss = 0.f;
        local += loss;
    }
    #pragma unroll
    for (int o = 16; o > 0; o >>= 1) local += __shfl_xor_sync(0xffffffffu, local, o);
    if ((tid & 31) == 0) red[tid >> 5] = local;
    __syncthreads();
    if (tid < 32) {
        float v = red[tid];
        #pragma unroll
        for (int o = 16; o > 0; o >>= 1) v += __shfl_xor_sync(0xffffffffu, v, o);
        if (tid == 0) out[0] = v / (float)ntok;
    }
}

// ---------------- host launch ----------------
extern "C" void kernel_launch(void* const* d_in, const int* in_sizes, int n_in,
                              void* d_out, int out_size)
{
    const float* inp    = (const float*)d_in[0];
    const int*   labels = (const int*)  d_in[1];
    const float* head_W = (const float*)d_in[2];
    const float* head_b = (const float*)d_in[3];
    const float* t0_pW  = (const float*)d_in[4];
    const float* t0_pb  = (const float*)d_in[5];
    const float* t0_W   = (const float*)d_in[6];
    const float* t0_b   = (const float*)d_in[7];
    const float* t1_pW  = (const float*)d_in[8];
    const float* t1_pb  = (const float*)d_in[9];
    const float* t1_W   = (const float*)d_in[10];
    const float* t1_b   = (const float*)d_in[11];
    const int ntok = in_sizes[1];   // 4096

    cudaFuncSetAttribute(gemm_ce_all, cudaFuncAttributeMaxDynamicSharedMemorySize, GEMM_SMEM);

    prep_kernel<<<PREP_TOTAL, 256>>>(inp, head_W, t0_W, t1_W);
    gather_kernel<<<1, 256>>>(labels, ntok);
    projs_kernel<<<1024, 256>>>(inp, t0_pW, t0_pb, t1_pW, t1_pb);
    gemm_ce_all<<<dim3(4, 96), 288, GEMM_SMEM>>>(head_b, t0_b, t1_b, labels);
    finalize_kernel<<<1, 1024>>>(labels, (float*)d_out, ntok);
}